// round 2
// baseline (speedup 1.0000x reference)
#include <cuda_runtime.h>
#include <math.h>

#define CB 2
#define CS 2048
#define CE 1024
#define CH 16
#define CD 64
#define CM (CB*CS)          // 4096 tokens
#define YAT_EPS 1e-5f

// Scratch (allocation-free rule: __device__ globals)
__device__ float g_q[(size_t)CM*CE];
__device__ float g_k[(size_t)CM*CE];
__device__ float g_v[(size_t)CM*CE];
__device__ float g_o[(size_t)CM*CE];

// ---------------------------------------------------------------------------
// C[M,N] = A[M,K] @ B[N,K]^T + bias[N]   (nn.Linear: x @ W.T + b)
// 128x128 tile, BK=16, 256 threads, 8x8 per thread.
// ---------------------------------------------------------------------------
__global__ __launch_bounds__(256) void gemm_nt_bias(
    const float* __restrict__ A, const float* __restrict__ B,
    const float* __restrict__ bias, float* __restrict__ C,
    int M, int N, int K)
{
    const int BM = 128, BN = 128, BK = 16;
    __shared__ float As[BK][BM + 4];
    __shared__ float Bs[BK][BN + 4];

    const int tid = threadIdx.x;
    const int tx = tid & 15;         // 0..15 (cols)
    const int ty = tid >> 4;         // 0..15 (rows)
    const int row0 = blockIdx.y * BM;
    const int col0 = blockIdx.x * BN;

    float acc[8][8];
#pragma unroll
    for (int i = 0; i < 8; i++)
#pragma unroll
        for (int j = 0; j < 8; j++) acc[i][j] = 0.0f;

    const int lr = tid >> 2;           // 0..63
    const int lc = (tid & 3) << 2;     // 0,4,8,12
    const float* Ab = A + (size_t)row0 * K;
    const float* Bb = B + (size_t)col0 * K;

    for (int k0 = 0; k0 < K; k0 += BK) {
#pragma unroll
        for (int rr = 0; rr < 2; rr++) {
            int r = lr + rr * 64;
            float4 va = *(const float4*)&Ab[(size_t)r * K + k0 + lc];
            As[lc + 0][r] = va.x; As[lc + 1][r] = va.y;
            As[lc + 2][r] = va.z; As[lc + 3][r] = va.w;
            float4 vb = *(const float4*)&Bb[(size_t)r * K + k0 + lc];
            Bs[lc + 0][r] = vb.x; Bs[lc + 1][r] = vb.y;
            Bs[lc + 2][r] = vb.z; Bs[lc + 3][r] = vb.w;
        }
        __syncthreads();
#pragma unroll
        for (int k = 0; k < BK; k++) {
            float ra[8], rb[8];
            *(float4*)&ra[0] = *(const float4*)&As[k][ty * 8];
            *(float4*)&ra[4] = *(const float4*)&As[k][ty * 8 + 4];
            *(float4*)&rb[0] = *(const float4*)&Bs[k][tx * 8];
            *(float4*)&rb[4] = *(const float4*)&Bs[k][tx * 8 + 4];
#pragma unroll
            for (int i = 0; i < 8; i++)
#pragma unroll
                for (int j = 0; j < 8; j++)
                    acc[i][j] = fmaf(ra[i], rb[j], acc[i][j]);
        }
        __syncthreads();
    }

#pragma unroll
    for (int i = 0; i < 8; i++) {
        size_t r = (size_t)(row0 + ty * 8 + i);
#pragma unroll
        for (int j0 = 0; j0 < 8; j0 += 4) {
            int c = col0 + tx * 8 + j0;
            float4 o;
            o.x = acc[i][j0 + 0] + bias[c + 0];
            o.y = acc[i][j0 + 1] + bias[c + 1];
            o.z = acc[i][j0 + 2] + bias[c + 2];
            o.w = acc[i][j0 + 3] + bias[c + 3];
            *(float4*)&C[r * N + c] = o;
        }
    }
}

// ---------------------------------------------------------------------------
// Fused YAT attention, flash-style online softmax.
// Grid: (S/64, H, B). Block: 256 threads (16x16). 64x64 q/kv tiles.
// smem (dynamic): Qst[64][64] (d-major), Kst[64][64] (d-major),
//                 Vs[64][64] (kv-major), Ps[64][68] (kv-major, padded)
// ---------------------------------------------------------------------------
__global__ __launch_bounds__(256) void yat_attention(
    const float* __restrict__ Qm, const float* __restrict__ Km,
    const float* __restrict__ Vm, float* __restrict__ Om,
    const float* __restrict__ alphap)
{
    extern __shared__ float sm[];
    float* Qst = sm;               // 64*64
    float* Kst = sm + 4096;        // 64*64
    float* Vs  = sm + 8192;        // 64*64
    float* Ps  = sm + 12288;       // 64*68

    const int tid = threadIdx.x;
    const int tx = tid & 15;       // kv-col group / d group
    const int ty = tid >> 4;       // q-row group
    const int b = blockIdx.z, h = blockIdx.y;
    const int q0 = blockIdx.x * 64;

    const float scale = powf(8.0f / logf(65.0f), alphap[0]);  // (sqrt(D)/log1p(D))^alpha

    // Load Q tile transposed: Qst[d][r]
    {
        int r = tid >> 2;
        int d0 = (tid & 3) << 4;
        const float* qp = &Qm[((size_t)(b * CS + q0 + r)) * CE + h * CD + d0];
#pragma unroll
        for (int u = 0; u < 4; u++) {
            float4 v = *(const float4*)(qp + u * 4);
            Qst[(d0 + u * 4 + 0) * 64 + r] = v.x;
            Qst[(d0 + u * 4 + 1) * 64 + r] = v.y;
            Qst[(d0 + u * 4 + 2) * 64 + r] = v.z;
            Qst[(d0 + u * 4 + 3) * 64 + r] = v.w;
        }
    }
    __syncthreads();

    // ||q||^2 for this thread's 4 rows
    float sqr[4] = {0.f, 0.f, 0.f, 0.f};
#pragma unroll 16
    for (int d = 0; d < 64; d++) {
        float4 qv = *(const float4*)&Qst[d * 64 + ty * 4];
        sqr[0] += qv.x * qv.x; sqr[1] += qv.y * qv.y;
        sqr[2] += qv.z * qv.z; sqr[3] += qv.w * qv.w;
    }

    float mrow[4], lrow[4], accO[4][4];
#pragma unroll
    for (int i = 0; i < 4; i++) {
        mrow[i] = -INFINITY; lrow[i] = 0.0f;
#pragma unroll
        for (int j = 0; j < 4; j++) accO[i][j] = 0.0f;
    }

    for (int t = 0; t < CS / 64; t++) {
        __syncthreads();   // protect Kst/Vs/Ps against previous iteration's readers
        {
            int r = tid >> 2;
            int d0 = (tid & 3) << 4;
            const float* kp = &Km[((size_t)(b * CS + t * 64 + r)) * CE + h * CD + d0];
            const float* vp = &Vm[((size_t)(b * CS + t * 64 + r)) * CE + h * CD + d0];
#pragma unroll
            for (int u = 0; u < 4; u++) {
                float4 kv = *(const float4*)(kp + u * 4);
                Kst[(d0 + u * 4 + 0) * 64 + r] = kv.x;
                Kst[(d0 + u * 4 + 1) * 64 + r] = kv.y;
                Kst[(d0 + u * 4 + 2) * 64 + r] = kv.z;
                Kst[(d0 + u * 4 + 3) * 64 + r] = kv.w;
                *(float4*)&Vs[r * 64 + d0 + u * 4] = *(const float4*)(vp + u * 4);
            }
        }
        __syncthreads();

        // S = Q K^T (with ||k||^2 fused into the same d-loop)
        float accS[4][4];
        float skc[4] = {0.f, 0.f, 0.f, 0.f};
#pragma unroll
        for (int i = 0; i < 4; i++)
#pragma unroll
            for (int j = 0; j < 4; j++) accS[i][j] = 0.0f;

#pragma unroll 16
        for (int d = 0; d < 64; d++) {
            float4 qv = *(const float4*)&Qst[d * 64 + ty * 4];
            float4 kv = *(const float4*)&Kst[d * 64 + tx * 4];
            float qa[4] = {qv.x, qv.y, qv.z, qv.w};
            float ka[4] = {kv.x, kv.y, kv.z, kv.w};
#pragma unroll
            for (int j = 0; j < 4; j++) {
                skc[j] = fmaf(ka[j], ka[j], skc[j]);
#pragma unroll
                for (int i = 0; i < 4; i++)
                    accS[i][j] = fmaf(qa[i], ka[j], accS[i][j]);
            }
        }

        // YAT score + online softmax (row groups of 16 lanes, xor-shfl reductions)
#pragma unroll
        for (int i = 0; i < 4; i++) {
            float s[4];
            float mx = -INFINITY;
#pragma unroll
            for (int j = 0; j < 4; j++) {
                float qk = accS[i][j];
                float dist = sqr[i] + skc[j] - 2.0f * qk + YAT_EPS;
                s[j] = scale * qk * qk / dist;
                mx = fmaxf(mx, s[j]);
            }
#pragma unroll
            for (int off = 8; off; off >>= 1)
                mx = fmaxf(mx, __shfl_xor_sync(0xffffffffu, mx, off));
            float mnew = fmaxf(mrow[i], mx);
            float corr = expf(mrow[i] - mnew);
            mrow[i] = mnew;
            float rs = 0.0f;
#pragma unroll
            for (int j = 0; j < 4; j++) {
                s[j] = expf(s[j] - mnew);
                rs += s[j];
            }
#pragma unroll
            for (int off = 8; off; off >>= 1)
                rs += __shfl_xor_sync(0xffffffffu, rs, off);
            lrow[i] = lrow[i] * corr + rs;
#pragma unroll
            for (int j = 0; j < 4; j++) accO[i][j] *= corr;
            // stash P transposed: Ps[kv][qrow]
#pragma unroll
            for (int j = 0; j < 4; j++)
                Ps[(tx * 4 + j) * 68 + ty * 4 + i] = s[j];
        }
        __syncthreads();

        // O += P @ V
#pragma unroll 8
        for (int j = 0; j < 64; j++) {
            float4 pv = *(const float4*)&Ps[j * 68 + ty * 4];
            float4 vv = *(const float4*)&Vs[j * 64 + tx * 4];
            float pa[4] = {pv.x, pv.y, pv.z, pv.w};
            float va[4] = {vv.x, vv.y, vv.z, vv.w};
#pragma unroll
            for (int i = 0; i < 4; i++)
#pragma unroll
                for (int jj = 0; jj < 4; jj++)
                    accO[i][jj] = fmaf(pa[i], va[jj], accO[i][jj]);
        }
    }

    // epilogue: divide by row sum, write [B,S,H,D]
#pragma unroll
    for (int i = 0; i < 4; i++) {
        float inv = 1.0f / lrow[i];
        float4 o;
        o.x = accO[i][0] * inv; o.y = accO[i][1] * inv;
        o.z = accO[i][2] * inv; o.w = accO[i][3] * inv;
        *(float4*)&Om[((size_t)(b * CS + q0 + ty * 4 + i)) * CE + h * CD + tx * 4] = o;
    }
}

// ---------------------------------------------------------------------------
extern "C" void kernel_launch(void* const* d_in, const int* in_sizes, int n_in,
                              void* d_out, int out_size)
{
    (void)in_sizes; (void)n_in; (void)out_size;
    const float* query = (const float*)d_in[0];
    const float* Wq    = (const float*)d_in[1];
    const float* bq    = (const float*)d_in[2];
    const float* Wk    = (const float*)d_in[3];
    const float* bk    = (const float*)d_in[4];
    const float* Wv    = (const float*)d_in[5];
    const float* bv    = (const float*)d_in[6];
    const float* Wo    = (const float*)d_in[7];
    const float* bo    = (const float*)d_in[8];
    const float* alpha = (const float*)d_in[9];

    float *q, *k, *v, *o;
    cudaGetSymbolAddress((void**)&q, g_q);
    cudaGetSymbolAddress((void**)&k, g_k);
    cudaGetSymbolAddress((void**)&v, g_v);
    cudaGetSymbolAddress((void**)&o, g_o);

    dim3 gg(CE / 128, CM / 128);   // (8, 32)
    gemm_nt_bias<<<gg, 256>>>(query, Wq, bq, q, CM, CE, CE);
    gemm_nt_bias<<<gg, 256>>>(query, Wk, bk, k, CM, CE, CE);
    gemm_nt_bias<<<gg, 256>>>(query, Wv, bv, v, CM, CE, CE);

    const size_t smem = (3 * 4096 + 64 * 68) * sizeof(float);   // 66560 B
    cudaFuncSetAttribute(yat_attention, cudaFuncAttributeMaxDynamicSharedMemorySize, (int)smem);
    yat_attention<<<dim3(CS / 64, CH, CB), 256, smem>>>(q, k, v, o, alpha);

    gemm_nt_bias<<<gg, 256>>>(o, Wo, bo, (float*)d_out, CM, CE, CE);
}